// round 11
// baseline (speedup 1.0000x reference)
#include <cuda_runtime.h>
#include <cuda_bf16.h>
#include <math.h>

#define LNUM   102
#define LSTART 100
#define LPAD   104
#define NT     128
#define MAXB   1024
#define SCALE  4.0f

__device__ int   g_perm[MAXB];
__device__ float g_vecF[MAXB][LPAD];
__device__ float g_vecB[MAXB][LPAD];
__device__ float g_CF[MAXB];
__device__ float g_CB[MAXB];
__device__ int   g_done[MAXB];      // zero-init; restored to 0 every launch

typedef __nv_bfloat162 bf2;

// ---------- counting sort (descending length) -> g_perm ----------
__global__ void sort_kernel(const int* __restrict__ lens, int B, int T) {
    __shared__ int hist[513];
    __shared__ int scan[513];
    __shared__ int off[513];
    const int tid = threadIdx.x;          // 1024 threads
    if (tid < 513) hist[tid] = 0;
    __syncthreads();
    int myLen = 0;
    if (tid < B) {
        myLen = lens[tid];
        if (myLen < 0) myLen = 0;
        if (myLen > T) myLen = T;
        if (myLen > 512) myLen = 512;
        atomicAdd(&hist[myLen], 1);
    }
    __syncthreads();
    if (tid < 513) scan[tid] = hist[512 - tid];
    __syncthreads();
    for (int d = 1; d < 513; d <<= 1) {
        int v = 0;
        if (tid < 513) { v = scan[tid]; if (tid >= d) v += scan[tid - d]; }
        __syncthreads();
        if (tid < 513) scan[tid] = v;
        __syncthreads();
    }
    if (tid < 513) off[tid] = scan[512 - tid] - hist[tid];
    __syncthreads();
    if (tid < B) {
        int pos = atomicAdd(&off[myLen], 1);
        g_perm[pos] = tid;
    }
}

// ---------- paired half-chain kernel: 2 same-direction chains per block ----------
__global__ __launch_bounds__(NT, 4)
void crf_pair_kernel(const float* __restrict__ logits,
                     const float* __restrict__ trans,
                     const int*   __restrict__ lens,
                     float* __restrict__ out,
                     int T, int B, int npair)
{
    const int  j    = threadIdx.x;
    const bool bwd  = (blockIdx.x >= npair);
    const int  pr   = bwd ? (blockIdx.x - npair) : blockIdx.x;
    const int  iA   = 2 * pr, iB = 2 * pr + 1;
    const int  bA   = g_perm[iA];
    const bool dupB = (iB >= B);
    const int  bB   = dupB ? bA : g_perm[iB];

    __shared__ __align__(16) __nv_bfloat16 qA_sh[2][LPAD];
    __shared__ __align__(16) __nv_bfloat16 qB_sh[2][LPAD];
    __shared__ int sdoA, sdoB;

    // E fragment: fwd rows of E, bwd rows of E^T — 52 bf16x2 (pads = 0)
    bf2 E2[52];
    #pragma unroll
    for (int mm = 0; mm < 52; ++mm) {
        float a = 0.f, c = 0.f;
        const int k = 2 * mm;
        if (j < LNUM) {
            if (!bwd) {
                const float* tr = trans + (size_t)j * LNUM;
                if (k + 0 < LNUM) a = __expf(tr[k + 0]);
                if (k + 1 < LNUM) c = __expf(tr[k + 1]);
            } else {
                if (k + 0 < LNUM) a = __expf(trans[(size_t)(k + 0) * LNUM + j]);
                if (k + 1 < LNUM) c = __expf(trans[(size_t)(k + 1) * LNUM + j]);
            }
        }
        E2[mm] = __floats2bfloat162_rn(a, c);
    }

    int lenA = lens[bA]; if (lenA > T) lenA = T; if (lenA < 0) lenA = 0;
    int lenB = lens[bB]; if (lenB > T) lenB = T; if (lenB < 0) lenB = 0;
    const int mA = lenA >> 1,          mB = lenB >> 1;
    const int nA = bwd ? (lenA - mA) : mA;
    const int nB = bwd ? (lenB - mB) : mB;
    const int nvA = bwd ? (nA - 1) : nA;
    const int nvB = bwd ? (nB - 1) : nB;
    const int n  = (nA > nB) ? nA : nB;

    const float* lgA = logits + (size_t)bA * T * LNUM;
    const float* lgB = logits + (size_t)bB * T * LNUM;

    // init vectors
    float qA, qB;
    if (!bwd) {
        qA = (j == LSTART) ? 1.f : 0.f;
        qB = qA;
    } else {
        const float vstop =
            (j < LNUM) ? __expf(trans[(size_t)(LNUM - 1) * LNUM + j]) : 0.f;
        qA = (lenA > 0)
           ? __expf(((j < LNUM) ? lgA[(size_t)(lenA - 1) * LNUM + j] : SCALE) - SCALE) * vstop
           : vstop;
        qB = (lenB > 0)
           ? __expf(((j < LNUM) ? lgB[(size_t)(lenB - 1) * LNUM + j] : SCALE) - SCALE) * vstop
           : vstop;
    }
    if (j < LPAD) {
        qA_sh[0][j] = __float2bfloat16(qA);  qA_sh[1][j] = __float2bfloat16(0.f);
        qB_sh[0][j] = __float2bfloat16(qB);  qB_sh[1][j] = __float2bfloat16(0.f);
    }

    const ptrdiff_t strd  = bwd ? -(ptrdiff_t)LNUM : (ptrdiff_t)LNUM;
    const float* lgcolA = lgA + (bwd ? (ptrdiff_t)(lenA - 2) * LNUM : 0) + j;
    const float* lgcolB = lgB + (bwd ? (ptrdiff_t)(lenB - 2) * LNUM : 0) + j;

    float CA = 0.f, CB = 0.f;

    // depth-4 register logit pipelines
    float lgqA[4], lgqB[4];
    #pragma unroll
    for (int u = 0; u < 4; ++u) {
        lgqA[u] = (u < nvA && j < LNUM) ? lgcolA[strd * u] : SCALE;
        lgqB[u] = (u < nvB && j < LNUM) ? lgcolB[strd * u] : SCALE;
    }

    __syncthreads();

    for (int tc = 0; tc < n; tc += 4) {
        float lgnA[4], lgnB[4];
        #pragma unroll
        for (int u = 0; u < 4; ++u) {
            const int sl = tc + 4 + u;
            lgnA[u] = (sl < nvA && j < LNUM) ? lgcolA[strd * sl] : SCALE;
            lgnB[u] = (sl < nvB && j < LNUM) ? lgcolB[strd * sl] : SCALE;
        }

        #pragma unroll
        for (int u = 0; u < 4; ++u) {
            const int t = tc + u;
            if (t >= n) break;                       // uniform across block

            const float elA = __expf(lgqA[u] - SCALE);
            const float elB = __expf(lgqB[u] - SCALE);
            const bool  do_max = ((t & 15) == 0) && (t > 0);

            // dual matvec, interleaved chains: 26 LDS.128 + 104 HFMA2
            const uint4* psA = reinterpret_cast<const uint4*>(qA_sh[t & 1]);
            const uint4* psB = reinterpret_cast<const uint4*>(qB_sh[t & 1]);

            uint4 va = psA[0], vb = psB[0];
            bf2 a0 = __hmul2(E2[0], *reinterpret_cast<bf2*>(&va.x));
            bf2 b0 = __hmul2(E2[0], *reinterpret_cast<bf2*>(&vb.x));
            bf2 a1 = __hmul2(E2[1], *reinterpret_cast<bf2*>(&va.y));
            bf2 b1 = __hmul2(E2[1], *reinterpret_cast<bf2*>(&vb.y));
            bf2 a2 = __hmul2(E2[2], *reinterpret_cast<bf2*>(&va.z));
            bf2 b2 = __hmul2(E2[2], *reinterpret_cast<bf2*>(&vb.z));
            bf2 a3 = __hmul2(E2[3], *reinterpret_cast<bf2*>(&va.w));
            bf2 b3 = __hmul2(E2[3], *reinterpret_cast<bf2*>(&vb.w));
            bf2 mxA = __floats2bfloat162_rn(0.f, 0.f), mxB = mxA;
            if (do_max) {
                mxA = __hmax2(__hmax2(*reinterpret_cast<bf2*>(&va.x),
                                      *reinterpret_cast<bf2*>(&va.y)),
                              __hmax2(*reinterpret_cast<bf2*>(&va.z),
                                      *reinterpret_cast<bf2*>(&va.w)));
                mxB = __hmax2(__hmax2(*reinterpret_cast<bf2*>(&vb.x),
                                      *reinterpret_cast<bf2*>(&vb.y)),
                              __hmax2(*reinterpret_cast<bf2*>(&vb.z),
                                      *reinterpret_cast<bf2*>(&vb.w)));
            }
            #pragma unroll
            for (int mm = 1; mm < 13; ++mm) {
                uint4 wa = psA[mm];
                uint4 wb = psB[mm];
                bf2 wa0 = *reinterpret_cast<bf2*>(&wa.x);
                bf2 wa1 = *reinterpret_cast<bf2*>(&wa.y);
                bf2 wa2 = *reinterpret_cast<bf2*>(&wa.z);
                bf2 wa3 = *reinterpret_cast<bf2*>(&wa.w);
                bf2 wb0 = *reinterpret_cast<bf2*>(&wb.x);
                bf2 wb1 = *reinterpret_cast<bf2*>(&wb.y);
                bf2 wb2 = *reinterpret_cast<bf2*>(&wb.z);
                bf2 wb3 = *reinterpret_cast<bf2*>(&wb.w);
                a0 = __hfma2(E2[4 * mm + 0], wa0, a0);
                b0 = __hfma2(E2[4 * mm + 0], wb0, b0);
                a1 = __hfma2(E2[4 * mm + 1], wa1, a1);
                b1 = __hfma2(E2[4 * mm + 1], wb1, b1);
                a2 = __hfma2(E2[4 * mm + 2], wa2, a2);
                b2 = __hfma2(E2[4 * mm + 2], wb2, b2);
                a3 = __hfma2(E2[4 * mm + 3], wa3, a3);
                b3 = __hfma2(E2[4 * mm + 3], wb3, b3);
                if (do_max) {
                    mxA = __hmax2(mxA, __hmax2(__hmax2(wa0, wa1), __hmax2(wa2, wa3)));
                    mxB = __hmax2(mxB, __hmax2(__hmax2(wb0, wb1), __hmax2(wb2, wb3)));
                }
            }
            bf2 sA = __hadd2(__hadd2(a0, a1), __hadd2(a2, a3));
            bf2 sB = __hadd2(__hadd2(b0, b1), __hadd2(b2, b3));
            float yA = __low2float(sA) + __high2float(sA);
            float yB = __low2float(sB) + __high2float(sB);

            if (do_max) {                            // uniform exact renorm
                if (t < nA) {
                    const float MA = fmaxf(
                        fmaxf(__low2float(mxA), __high2float(mxA)), 1e-30f);
                    yA *= __fdividef(1.f, MA);
                    CA += __logf(MA);
                }
                if (t < nB) {
                    const float MB = fmaxf(
                        fmaxf(__low2float(mxB), __high2float(mxB)), 1e-30f);
                    yB *= __fdividef(1.f, MB);
                    CB += __logf(MB);
                }
            }

            qA = (t < nA) ? elA * yA : qA;           // frozen chain keeps q
            qB = (t < nB) ? elB * yB : qB;
            if (j < LPAD) {
                qA_sh[(t + 1) & 1][j] = __float2bfloat16(qA);
                qB_sh[(t + 1) & 1][j] = __float2bfloat16(qB);
            }
            __syncthreads();                         // single barrier per step
        }

        #pragma unroll
        for (int u = 0; u < 4; ++u) { lgqA[u] = lgnA[u]; lgqB[u] = lgnB[u]; }
    }

    // ---- publish half vectors + constants ----
    if (j < LPAD) {
        if (!bwd) {
            g_vecF[bA][j] = qA;
            if (!dupB) g_vecF[bB][j] = qB;
        } else {
            g_vecB[bA][j] = qA;
            if (!dupB) g_vecB[bB][j] = qB;
        }
    }
    if (j == 0) {
        if (!bwd) { g_CF[bA] = CA + SCALE * (float)nA;
                    if (!dupB) g_CF[bB] = CB + SCALE * (float)nB; }
        else      { g_CB[bA] = CA + SCALE * (float)nA;
                    if (!dupB) g_CB[bB] = CB + SCALE * (float)nB; }
    }
    __threadfence();
    __syncthreads();

    // ---- fused combine: second arriver per batch computes the dot ----
    if (j == 0)  sdoA = (atomicAdd(&g_done[bA], 1) == 1);
    if (j == 32) sdoB = dupB ? 0 : (atomicAdd(&g_done[bB], 1) == 1);
    __syncthreads();

    const int w = j >> 5, l = j & 31;
    if ((w == 0 && sdoA) || (w == 1 && sdoB)) {
        const int bb = (w == 0) ? bA : bB;
        __threadfence();
        double s = 0.0;
        #pragma unroll
        for (int k = l; k < LPAD; k += 32)
            s += (double)__ldcg(&g_vecF[bb][k]) * (double)__ldcg(&g_vecB[bb][k]);
        #pragma unroll
        for (int o = 16; o; o >>= 1)
            s += __shfl_xor_sync(0xffffffffu, s, o);
        if (l == 0) {
            out[bb] = __ldcg(&g_CF[bb]) + __ldcg(&g_CB[bb]) + (float)log(s);
            g_done[bb] = 0;                          // restore for next replay
        }
    }
}

extern "C" void kernel_launch(void* const* d_in, const int* in_sizes, int n_in,
                              void* d_out, int out_size)
{
    const float* logits = (const float*)d_in[0];   // [B, T, L] f32
    const float* trans  = (const float*)d_in[1];   // [L, L]    f32
    const int*   lens   = (const int*)d_in[2];     // [B]       i32
    float*       out    = (float*)d_out;           // [B]       f32

    const int B = in_sizes[2];
    const int T = in_sizes[0] / (B * LNUM);
    const int npair = (B + 1) / 2;

    sort_kernel<<<1, 1024>>>(lens, B, T);
    crf_pair_kernel<<<2 * npair, NT>>>(logits, trans, lens, out, T, B, npair);
}

// round 12
// speedup vs baseline: 1.2375x; 1.2375x over previous
#include <cuda_runtime.h>
#include <cuda_bf16.h>
#include <math.h>

#define LNUM   102
#define LSTART 100
#define LPAD   104
#define NT     128
#define MAXB   1024
#define SCALE  4.0f

__device__ int   g_perm[MAXB];
__device__ float g_vecF[MAXB][LPAD];
__device__ float g_vecB[MAXB][LPAD];
__device__ float g_CF[MAXB];
__device__ float g_CB[MAXB];
__device__ int   g_done[MAXB];        // zero-init; each launch restores to 0

typedef __nv_bfloat162 bf2;

// ---------- counting sort (descending length) -> g_perm ----------
__global__ void sort_kernel(const int* __restrict__ lens, int B, int T) {
    __shared__ int hist[513];
    __shared__ int scan[513];
    __shared__ int off[513];
    const int tid = threadIdx.x;          // 1024 threads
    if (tid < 513) hist[tid] = 0;
    __syncthreads();
    int myLen = 0;
    if (tid < B) {
        myLen = lens[tid];
        if (myLen < 0) myLen = 0;
        if (myLen > T) myLen = T;
        if (myLen > 512) myLen = 512;
        atomicAdd(&hist[myLen], 1);
    }
    __syncthreads();
    if (tid < 513) scan[tid] = hist[512 - tid];
    __syncthreads();
    for (int d = 1; d < 513; d <<= 1) {
        int v = 0;
        if (tid < 513) { v = scan[tid]; if (tid >= d) v += scan[tid - d]; }
        __syncthreads();
        if (tid < 513) scan[tid] = v;
        __syncthreads();
    }
    if (tid < 513) off[tid] = scan[512 - tid] - hist[tid];
    __syncthreads();
    if (tid < B) {
        int pos = atomicAdd(&off[myLen], 1);
        g_perm[pos] = tid;
    }
}

// ---------- half-chain kernel (fwd E / bwd E^T), bf16 engine, fused combine ----------
__global__ __launch_bounds__(NT, 4)
void crf_half_kernel(const float* __restrict__ logits,
                     const float* __restrict__ trans,
                     const int*   __restrict__ lens,
                     float* __restrict__ out,
                     int T)
{
    const int  j    = threadIdx.x;
    const int  rank = blockIdx.x >> 1;
    const bool bwd  = (blockIdx.x & 1) != 0;
    const int  b    = g_perm[rank];

    __shared__ __align__(16) __nv_bfloat16 q_sh[2][LPAD];
    __shared__ int sdo;

    int len = lens[b];
    if (len > T) len = T;
    if (len < 0) len = 0;
    const int m  = len >> 1;
    const int n  = bwd ? (len - m) : m;       // steps this half runs
    const int nv = bwd ? (n - 1) : n;         // # valid logit reads in-loop

    // E fragment: fwd rows of E, bwd rows of E^T — 52 bf16x2 (pads = 0)
    bf2 E2[52];
    #pragma unroll
    for (int mm = 0; mm < 52; ++mm) {
        float a = 0.f, c = 0.f;
        const int k = 2 * mm;
        if (j < LNUM) {
            if (!bwd) {
                const float* tr = trans + (size_t)j * LNUM;
                if (k + 0 < LNUM) a = __expf(tr[k + 0]);
                if (k + 1 < LNUM) c = __expf(tr[k + 1]);
            } else {
                if (k + 0 < LNUM) a = __expf(trans[(size_t)(k + 0) * LNUM + j]);
                if (k + 1 < LNUM) c = __expf(trans[(size_t)(k + 1) * LNUM + j]);
            }
        }
        E2[mm] = __floats2bfloat162_rn(a, c);
    }

    const float* lg = logits + (size_t)b * T * LNUM;

    // init vector
    float q;
    if (!bwd) {
        q = (j == LSTART) ? 1.f : 0.f;
    } else {
        float vstop = (j < LNUM) ? __expf(trans[(size_t)(LNUM - 1) * LNUM + j]) : 0.f;
        if (len > 0) {
            float lgl = (j < LNUM) ? lg[(size_t)(len - 1) * LNUM + j] : SCALE;
            q = __expf(lgl - SCALE) * vstop;
        } else {
            q = vstop;
        }
    }
    if (j < LPAD) {
        q_sh[0][j] = __float2bfloat16(q);
        q_sh[1][j] = __float2bfloat16(0.f);
    }

    // logit addressing: step s reads row (fwd: s) / (bwd: len-2-s)
    const ptrdiff_t strd = bwd ? -(ptrdiff_t)LNUM : (ptrdiff_t)LNUM;
    const ptrdiff_t row0 = bwd ? (ptrdiff_t)(len - 2) * LNUM : 0;
    const float* lgcol = lg + row0 + j;

    float C = 0.f;

    // depth-4 register logit pipeline
    float lgq[4];
    #pragma unroll
    for (int u = 0; u < 4; ++u)
        lgq[u] = (u < nv && j < LNUM) ? lgcol[strd * u] : SCALE;

    __syncthreads();

    for (int tc = 0; tc < n; tc += 4) {
        // prefetch next chunk (MLP=4)
        float lgn[4];
        #pragma unroll
        for (int u = 0; u < 4; ++u) {
            const int sl = tc + 4 + u;
            lgn[u] = (sl < nv && j < LNUM) ? lgcol[strd * sl] : SCALE;
        }

        #pragma unroll
        for (int u = 0; u < 4; ++u) {
            const int t = tc + u;
            if (t >= n) break;                  // uniform across block

            const float el = __expf(lgq[u] - SCALE);
            const bool do_max = ((t & 15) == 0) && (t > 0);

            // y[j] = sum_k E[j,k] * q[k] — 13 LDS.128 + 52 HFMA2 (bf16x2)
            const uint4* ps = reinterpret_cast<const uint4*>(q_sh[t & 1]);
            uint4 v = ps[0];
            bf2 v0 = *reinterpret_cast<bf2*>(&v.x);
            bf2 v1 = *reinterpret_cast<bf2*>(&v.y);
            bf2 v2 = *reinterpret_cast<bf2*>(&v.z);
            bf2 v3 = *reinterpret_cast<bf2*>(&v.w);
            bf2 a0 = __hmul2(E2[0], v0);
            bf2 a1 = __hmul2(E2[1], v1);
            bf2 a2 = __hmul2(E2[2], v2);
            bf2 a3 = __hmul2(E2[3], v3);
            bf2 mx = __floats2bfloat162_rn(0.f, 0.f);
            if (do_max)
                mx = __hmax2(__hmax2(v0, v1), __hmax2(v2, v3));
            #pragma unroll
            for (int mm = 1; mm < 13; ++mm) {
                uint4 w = ps[mm];
                bf2 w0 = *reinterpret_cast<bf2*>(&w.x);
                bf2 w1 = *reinterpret_cast<bf2*>(&w.y);
                bf2 w2 = *reinterpret_cast<bf2*>(&w.z);
                bf2 w3 = *reinterpret_cast<bf2*>(&w.w);
                a0 = __hfma2(E2[4 * mm + 0], w0, a0);
                a1 = __hfma2(E2[4 * mm + 1], w1, a1);
                a2 = __hfma2(E2[4 * mm + 2], w2, a2);
                a3 = __hfma2(E2[4 * mm + 3], w3, a3);
                if (do_max)
                    mx = __hmax2(mx, __hmax2(__hmax2(w0, w1), __hmax2(w2, w3)));
            }
            bf2 s2 = __hadd2(__hadd2(a0, a1), __hadd2(a2, a3));
            float y = __low2float(s2) + __high2float(s2);

            if (do_max) {                       // uniform exact renorm every 16 steps
                const float M = fmaxf(
                    fmaxf(__low2float(mx), __high2float(mx)), 1e-30f);
                y *= __fdividef(1.f, M);
                C += __logf(M);
            }

            q = el * y;                         // pads: E2=0 -> y=0 -> q=0
            if (j < LPAD) q_sh[(t + 1) & 1][j] = __float2bfloat16(q);
            __syncthreads();
        }

        #pragma unroll
        for (int u = 0; u < 4; ++u) lgq[u] = lgn[u];
    }

    // ---- publish this half's vector + scale constant ----
    if (j < LPAD) {
        if (!bwd) g_vecF[b][j] = q;
        else      g_vecB[b][j] = q;
    }
    if (j == 0) {
        const float Ctot = C + SCALE * (float)n;
        if (!bwd) g_CF[b] = Ctot;
        else      g_CB[b] = Ctot;
    }
    __threadfence();
    __syncthreads();

    // ---- fused combine: second arriver computes out[b] ----
    if (j == 0) sdo = (atomicAdd(&g_done[b], 1) == 1);
    __syncthreads();

    if (sdo && j < 32) {
        __threadfence();
        double s = 0.0;
        #pragma unroll
        for (int k = j; k < LPAD; k += 32)
            s += (double)__ldcg(&g_vecF[b][k]) * (double)__ldcg(&g_vecB[b][k]);
        #pragma unroll
        for (int o = 16; o; o >>= 1)
            s += __shfl_xor_sync(0xffffffffu, s, o);
        if (j == 0) {
            out[b] = __ldcg(&g_CF[b]) + __ldcg(&g_CB[b]) + (float)log(s);
            g_done[b] = 0;                      // restore for next graph replay
        }
    }
}

extern "C" void kernel_launch(void* const* d_in, const int* in_sizes, int n_in,
                              void* d_out, int out_size)
{
    const float* logits = (const float*)d_in[0];   // [B, T, L] f32
    const float* trans  = (const float*)d_in[1];   // [L, L]    f32
    const int*   lens   = (const int*)d_in[2];     // [B]       i32
    float*       out    = (float*)d_out;           // [B]       f32

    const int B = in_sizes[2];
    const int T = in_sizes[0] / (B * LNUM);

    sort_kernel<<<1, 1024>>>(lens, B, T);
    crf_half_kernel<<<2 * B, NT>>>(logits, trans, lens, out, T);
}